// round 3
// baseline (speedup 1.0000x reference)
#include <cuda_runtime.h>

#define NW 6
#define NL 4
#define HP 112
#define WP 112
#define NB 8
#define OC 16

__device__ float g_T[6*27];

// ---------------------------------------------------------------------------
// Kernel 0 (v3): one warp per basis state, warp-local sync only.
// Each layer = 6 single-qubit butterflies + ONE composite index permutation
// (the CNOT ring is GF(2)-linear on basis indices).
// Then M_w = Phi^dag Z_w Phi -> fold (-i)^popcount -> 27-term trig table.
// ---------------------------------------------------------------------------
__global__ void k_precompute(const float* __restrict__ w)
{
    __shared__ float2 sU[24][4];          // u00,u01,u10,u11 per gate
    __shared__ float2 phi[8][64];
    __shared__ float  Mre[6][8][8];
    __shared__ float  Mim[6][8][8];

    const int tid  = threadIdx.x;         // 256 threads = 8 warps
    const int wrp  = tid >> 5;            // basis state j = warp id
    const int lane = tid & 31;

    if (tid < 24) {
        const float ph = w[tid*3 + 0];
        const float th = w[tid*3 + 1];
        const float om = w[tid*3 + 2];
        const float ch = cosf(0.5f * th), sh = sinf(0.5f * th);
        float cp, sp, cm, sm;
        sincosf(-0.5f * (ph + om), &sp, &cp);   // ep = cp + i sp
        sincosf(-0.5f * (ph - om), &sm, &cm);   // em = cm + i sm
        sU[tid][0] = make_float2( cp*ch,  sp*ch);
        sU[tid][1] = make_float2(-cm*sh,  sm*sh);
        sU[tid][2] = make_float2( cm*sh,  sm*sh);
        sU[tid][3] = make_float2( cp*ch, -sp*ch);
    }
    // init: phi[j] = |j>|000>
    {
        const int s0 = lane, s1 = lane + 32;
        phi[wrp][s0] = make_float2((s0 == wrp * 8) ? 1.f : 0.f, 0.f);
        phi[wrp][s1] = make_float2((s1 == wrp * 8) ? 1.f : 0.f, 0.f);
    }
    __syncthreads();

    float2* st = phi[wrp];
    for (int l = 0; l < NL; l++) {
        // 6 single-qubit gates: each lane owns one butterfly pair
        #pragma unroll
        for (int q = 0; q < NW; q++) {
            const int stride = 1 << (5 - q);
            const int s0 = ((lane & ~(stride - 1)) << 1) | (lane & (stride - 1));
            const int s1 = s0 | stride;
            const float2 u00 = sU[l*6+q][0], u01 = sU[l*6+q][1];
            const float2 u10 = sU[l*6+q][2], u11 = sU[l*6+q][3];
            const float2 a0 = st[s0], a1 = st[s1];
            st[s0] = make_float2(
                u00.x*a0.x - u00.y*a0.y + u01.x*a1.x - u01.y*a1.y,
                u00.x*a0.y + u00.y*a0.x + u01.x*a1.y + u01.y*a1.x);
            st[s1] = make_float2(
                u10.x*a0.x - u10.y*a0.y + u11.x*a1.x - u11.y*a1.y,
                u10.x*a0.y + u10.y*a0.x + u11.x*a1.y + u11.y*a1.x);
            __syncwarp();
        }
        // CNOT ring as one composite permutation:
        // Final[s] = old[g_0(g_1(...g_5(s)))] (apply g_w for w = 5..0)
        const int r = l % (NW - 1) + 1;
        int i0 = lane, i1 = lane + 32;
        #pragma unroll
        for (int q = NW - 1; q >= 0; q--) {
            const int cpos = 5 - q;
            const int tpos = 5 - ((q + r) % NW);
            i0 ^= ((i0 >> cpos) & 1) << tpos;
            i1 ^= ((i1 >> cpos) & 1) << tpos;
        }
        const float2 v0 = st[i0], v1 = st[i1];
        __syncwarp();
        st[lane] = v0;
        st[lane + 32] = v1;
        __syncwarp();
    }
    __syncthreads();

    // M_w[i][jj] = sum_s z_w(s) conj(phi_i[s]) phi_jj[s]
    for (int e = tid; e < 6 * 64; e += blockDim.x) {
        const int q = e / 64, ij = e % 64, i = ij / 8, jj = ij % 8;
        float re = 0.f, im = 0.f;
        #pragma unroll 8
        for (int t = 0; t < 64; t++) {
            const float z = ((t >> (5 - q)) & 1) ? -1.f : 1.f;
            const float2 a = phi[i][t], b = phi[jj][t];
            re += z * (a.x * b.x + a.y * b.y);
            im += z * (a.x * b.y - a.y * b.x);
        }
        Mre[q][i][jj] = re;
        Mim[q][i][jj] = im;
    }
    __syncthreads();

    // half-angle pair products -> {1, cos a, sin a} basis table
    if (tid < 6 * 27) {
        const int q = tid / 27, term = tid % 27;
        const int tt[3] = { term / 9, (term / 3) % 3, term % 3 };
        float acc = 0.f;
        for (int i = 0; i < 8; i++) {
            for (int jj = 0; jj < 8; jj++) {
                const int k = (__popc(i) - __popc(jj)) & 3;
                const float mre = Mre[q][i][jj], mim = Mim[q][i][jj];
                float f = (k == 0) ? mre : (k == 1) ? -mim : (k == 2) ? -mre : mim;
                #pragma unroll
                for (int c = 0; c < 3; c++) {
                    const int bi = (i >> (2 - c)) & 1;
                    const int bj = (jj >> (2 - c)) & 1;
                    const int t = tt[c];
                    float pc;
                    if (bi == bj)
                        pc = (t == 0) ? 0.5f : (t == 1) ? (bi ? -0.5f : 0.5f) : 0.f;
                    else
                        pc = (t == 2) ? 0.5f : 0.f;
                    f *= pc;
                }
                acc += f;
            }
        }
        g_T[tid] = acc;
    }
}

// ---------------------------------------------------------------------------
// Kernel 1 (fused pixels + resize): block = 16x16 patch tile.
// Phase 1: compute y for the 18x18 halo region (clamped coords) -> shared.
// Phase 2: each thread emits its 2x2 output quad for all 16 channels.
// ---------------------------------------------------------------------------
__global__ void k_fused(const float* __restrict__ x,
                        const float* __restrict__ fcw,
                        const float* __restrict__ fcb,
                        const float* __restrict__ lng,
                        const float* __restrict__ lnb,
                        float* __restrict__ out)
{
    __shared__ float sy[OC][18][18];
    __shared__ float sT[162], sFC[96], sFB[16], sG[16], sB[16];

    const int tid = threadIdx.x;
    if (tid < 162) sT[tid] = g_T[tid];
    if (tid < 96)  sFC[tid] = fcw[tid];
    if (tid >= 96  && tid < 112) sFB[tid - 96]  = fcb[tid - 96];
    if (tid >= 112 && tid < 128) sG [tid - 112] = lng[tid - 112];
    if (tid >= 128 && tid < 144) sB [tid - 128] = lnb[tid - 128];
    __syncthreads();

    const int b   = blockIdx.z;
    const int bh0 = blockIdx.y * 16;
    const int bw0 = blockIdx.x * 16;

    // Phase 1: 324 halo pixels over 256 threads
    for (int i = tid; i < 18 * 18; i += 256) {
        const int r = i / 18, c = i % 18;
        const int hp = min(max(bh0 - 1 + r, 0), HP - 1);
        const int wp = min(max(bw0 - 1 + c, 0), WP - 1);

        float g[3][3];
        #pragma unroll
        for (int ch = 0; ch < 3; ch++) {
            const float* base = x + (((long)(b * 3 + ch) * 224 + 2 * hp) * 224 + 2 * wp);
            const float2 r0 = *reinterpret_cast<const float2*>(base);
            const float2 r1 = *reinterpret_cast<const float2*>(base + 224);
            const float a = 0.25f * (r0.x + r0.y + r1.x + r1.y);
            float sn, cs;
            sincosf(a, &sn, &cs);
            g[ch][0] = 1.f; g[ch][1] = cs; g[ch][2] = sn;
        }

        float e[6];
        #pragma unroll
        for (int q = 0; q < 6; q++) e[q] = 0.f;
        #pragma unroll
        for (int t0 = 0; t0 < 3; t0++)
            #pragma unroll
            for (int t1 = 0; t1 < 3; t1++) {
                const float p01 = g[0][t0] * g[1][t1];
                #pragma unroll
                for (int t2 = 0; t2 < 3; t2++) {
                    const float bas = p01 * g[2][t2];
                    const int t = (t0 * 3 + t1) * 3 + t2;
                    #pragma unroll
                    for (int q = 0; q < 6; q++) e[q] += sT[q * 27 + t] * bas;
                }
            }

        float y[OC], mu = 0.f;
        #pragma unroll
        for (int o = 0; o < OC; o++) {
            float acc = sFB[o];
            #pragma unroll
            for (int q = 0; q < 6; q++) acc += sFC[o * 6 + q] * e[q];
            y[o] = acc;
            mu += acc;
        }
        mu *= (1.f / OC);
        float var = 0.f;
        #pragma unroll
        for (int o = 0; o < OC; o++) { const float d = y[o] - mu; var += d * d; }
        var *= (1.f / OC);
        const float inv = rsqrtf(var + 1e-5f);
        #pragma unroll
        for (int o = 0; o < OC; o++)
            sy[o][r][c] = fmaxf((y[o] - mu) * inv * sG[o] + sB[o], 0.f);
    }
    __syncthreads();

    // Phase 2: bilinear 2x upsample (jax half-pixel weights 0.25/0.75)
    const int tx = tid & 15, ty = tid >> 4;
    const int oh = 2 * (bh0 + ty);
    const int ow = 2 * (bw0 + tx);
    const int r0 = ty, r1 = ty + 1, r2 = ty + 2;
    const int c0 = tx, c1 = tx + 1, c2 = tx + 2;

    #pragma unroll
    for (int o = 0; o < OC; o++) {
        const float a0 = 0.25f * sy[o][r0][c0] + 0.75f * sy[o][r0][c1];
        const float b0 = 0.75f * sy[o][r0][c1] + 0.25f * sy[o][r0][c2];
        const float a1 = 0.25f * sy[o][r1][c0] + 0.75f * sy[o][r1][c1];
        const float b1 = 0.75f * sy[o][r1][c1] + 0.25f * sy[o][r1][c2];
        const float a2 = 0.25f * sy[o][r2][c0] + 0.75f * sy[o][r2][c1];
        const float b2 = 0.75f * sy[o][r2][c1] + 0.25f * sy[o][r2][c2];

        float* obase = out + (((long)(b * OC + o) * 224 + oh) * 224 + ow);
        *reinterpret_cast<float2*>(obase) =
            make_float2(0.25f * a0 + 0.75f * a1, 0.25f * b0 + 0.75f * b1);
        *reinterpret_cast<float2*>(obase + 224) =
            make_float2(0.75f * a1 + 0.25f * a2, 0.75f * b1 + 0.25f * b2);
    }
}

extern "C" void kernel_launch(void* const* d_in, const int* in_sizes, int n_in,
                              void* d_out, int out_size)
{
    const float* x   = (const float*)d_in[0];
    const float* wts = (const float*)d_in[1];
    const float* fcw = (const float*)d_in[2];
    const float* fcb = (const float*)d_in[3];
    const float* lng = (const float*)d_in[4];
    const float* lnb = (const float*)d_in[5];
    float* out = (float*)d_out;

    k_precompute<<<1, 256>>>(wts);
    dim3 fg(WP / 16, HP / 16, NB);
    k_fused<<<fg, 256>>>(x, fcw, fcb, lng, lnb, out);
}